// round 17
// baseline (speedup 1.0000x reference)
#include <cuda_runtime.h>
#include <cuda_bf16.h>
#include <cstdint>
#include <math.h>

// ---------------- problem constants ----------------
#define NB    64
#define NCIN  3
#define NHID  128
#define NK    1024

#define S1    31          // conv1 out spatial
#define P1    961         // 31*31
#define S2    30          // conv2 out spatial
#define P2    900         // 30*30
#define NROWS 57600       // 64*900 flat VQ rows
#define NELEMF 7372800.0  // 64*128*900

#define VQ_ROWS 128
#define VQ_MARGIN 6e-5f
#define RISK_THR 4e-6f

// ---------------- scratch (device globals; no allocation allowed) ----------
__device__ float  g_z1[NB * NHID * P1];   // encoder conv1 out (relu) -- EXACT
__device__ float  g_z [NB * NHID * P2];   // encoder conv2 out (relu) -- approx
__device__ float  g_y [NB * NHID * P1];   // dec1 out (relu)
__device__ float  g_cnorm[NK];
__device__ float  g_znorm[NROWS];
__device__ int    g_counts[NK];
__device__ double g_sse;
__device__ __align__(16) __nv_bfloat16 g_whi[NHID * 512];    // dec_w1 hi [co][k]
__device__ __align__(16) __nv_bfloat16 g_wlo[NHID * 512];    // dec_w1 lo
__device__ __align__(16) __nv_bfloat16 g_w2hi[NHID * 512];   // enc_w2 hi [co][k']
__device__ __align__(16) __nv_bfloat16 g_w2lo[NHID * 512];   // enc_w2 lo
__device__ __align__(16) __nv_bfloat16 g_cbhi[NK * NHID];    // codebook hi
__device__ __align__(16) __nv_bfloat16 g_cblo[NK * NHID];
__device__ __align__(16) __nv_bfloat16 g_qhi[NB * NHID * P2];
__device__ __align__(16) __nv_bfloat16 g_qlo[NB * NHID * P2];

// ---------------- helpers ----------------
#define MMA_BF16(d, a0, a1, a2, a3, b0, b1)                                   \
    asm volatile(                                                             \
        "mma.sync.aligned.m16n8k16.row.col.f32.bf16.bf16.f32 "                \
        "{%0,%1,%2,%3}, {%4,%5,%6,%7}, {%8,%9}, {%0,%1,%2,%3};"               \
        : "+f"(d[0]), "+f"(d[1]), "+f"(d[2]), "+f"(d[3])                      \
        : "r"(a0), "r"(a1), "r"(a2), "r"(a3), "r"(b0), "r"(b1))

#define LDSM_X4(r0, r1, r2, r3, a)                                            \
    asm volatile("ldmatrix.sync.aligned.m8n8.x4.shared.b16 {%0,%1,%2,%3}, [%4];" \
        : "=r"(r0), "=r"(r1), "=r"(r2), "=r"(r3) : "r"(a))

#define TOP3(val, idx, v0, v1, v2, i0, i1, i2)                                \
    if ((val) < (v2)) {                                                       \
        if ((val) < (v1)) {                                                   \
            if ((val) < (v0)) { v2 = v1; i2 = i1; v1 = v0; i1 = i0;           \
                                v0 = (val); i0 = (idx); }                     \
            else { v2 = v1; i2 = i1; v1 = (val); i1 = (idx); }                \
        } else { v2 = (val); i2 = (idx); }                                    \
    }

__device__ __forceinline__ uint32_t smaddr(const void* p) {
    return (uint32_t)__cvta_generic_to_shared(p);
}

__device__ __forceinline__ void cp_async16(void* dst, const void* src) {
    unsigned s = (unsigned)__cvta_generic_to_shared(dst);
    asm volatile("cp.async.ca.shared.global [%0], [%1], 16;" :: "r"(s), "l"(src));
}
#define CP_COMMIT asm volatile("cp.async.commit_group;")
#define CP_WAIT1  asm volatile("cp.async.wait_group 1;")
#define CP_WAIT0  asm volatile("cp.async.wait_group 0;")

// ---------------- prep: zero + cnorm + splits (one kernel) ---------------
__global__ void k_prep(const float* __restrict__ cb,
                       const float* __restrict__ dw1,
                       const float* __restrict__ ew2) {
    int e = blockIdx.x * 256 + threadIdx.x;   // 131072 threads
    if (e < NK * NHID) {
        float v = cb[e];
        __nv_bfloat16 h = __float2bfloat16(v);
        g_cbhi[e] = h;
        g_cblo[e] = __float2bfloat16(v - __bfloat162float(h));
    }
    if (e < NHID * 512) {
        int co = e >> 9, k = e & 511;
        // dec_w1: [ci][co][kh][kw], k = ci*4 + tap
        {
            float v = dw1[(k >> 2) * 512 + co * 4 + (k & 3)];
            __nv_bfloat16 h = __float2bfloat16(v);
            g_whi[e] = h;
            g_wlo[e] = __float2bfloat16(v - __bfloat162float(h));
        }
        // enc_w2: [co][ci][kh][kw], k' = tap*128 + ci
        {
            int ci = k & 127, tap = k >> 7;
            float v = ew2[co * 512 + ci * 4 + tap];
            __nv_bfloat16 h = __float2bfloat16(v);
            g_w2hi[e] = h;
            g_w2lo[e] = __float2bfloat16(v - __bfloat162float(h));
        }
    }
    if (e < NK) {
        g_counts[e] = 0;
        const float* p = cb + e * NHID;
        float s = 0.f;
        for (int d = 0; d < NHID; d++) {
            float m = __fmul_rn(p[d], p[d]);
            s = __fadd_rn(s, m);
        }
        g_cnorm[e] = s;
    }
    if (e == 0) g_sse = 0.0;
}

// ---------------- |z|^2 per flat row: strict sequential ------------------
__global__ void __launch_bounds__(256) k_znorm() {
    __shared__ float s[64 * 129];
    int row0 = blockIdx.x * 64;
    int tid = threadIdx.x;
#pragma unroll
    for (int it = 0; it < 32; it++) {
        int e = tid + 256 * it;
        int r = e >> 7, d = e & 127;
        s[r * 129 + d] = g_z[row0 * NHID + e];
    }
    __syncthreads();
    if (tid < 64) {
        const float* p = s + tid * 129;
        float acc = 0.f;
        for (int d = 0; d < 128; d++) {
            float m = __fmul_rn(p[d], p[d]);
            acc = __fadd_rn(acc, m);
        }
        g_znorm[row0 + tid] = acc;
    }
}

// ---------------- conv1: 3->128, k4, s2, relu (EXACT smem GEMM) ----------
__global__ void __launch_bounds__(256) k_conv1(const float* __restrict__ x,
                                               const float* __restrict__ w,
                                               const float* __restrict__ bias) {
    __shared__ __align__(16) float As[48 * 132];   // [k][co]
    __shared__ __align__(16) float Bs[48 * 68];    // [k][pos]
    int b = blockIdx.y;
    int posbase = blockIdx.x * 64;
    int tid = threadIdx.x, tx = tid & 15, ty = tid >> 4;
    const float* xb = x + b * (NCIN * 64 * 64);

    for (int e = tid; e < 48 * 128; e += 256) {
        int co = e / 48, kl = e - co * 48;
        int kh = kl / 12, r2 = kl - kh * 12;
        int kw = r2 / 3, ci = r2 - kw * 3;
        As[kl * 132 + co] = w[co * 48 + ci * 16 + kh * 4 + kw];
    }
    for (int e = tid; e < 48 * 64; e += 256) {
        int pl = e & 63, kl = e >> 6;
        int kh = kl / 12, r2 = kl - kh * 12;
        int kw = r2 / 3, ci = r2 - kw * 3;
        int pos = posbase + pl;
        float v = 0.f;
        if (pos < P1) {
            int oh = pos / S1, ow = pos - oh * S1;
            v = xb[ci * 4096 + (oh * 2 + kh) * 64 + (ow * 2 + kw)];
        }
        Bs[kl * 68 + pl] = v;
    }
    __syncthreads();

    float acc[8][4];
#pragma unroll
    for (int i = 0; i < 8; i++)
#pragma unroll
        for (int j = 0; j < 4; j++) acc[i][j] = 0.f;

#pragma unroll 8
    for (int kl = 0; kl < 48; kl++) {
        float4 a0 = *(const float4*)(As + kl * 132 + 4 * ty);
        float4 a1 = *(const float4*)(As + kl * 132 + 64 + 4 * ty);
        float4 b0 = *(const float4*)(Bs + kl * 68 + 4 * tx);
        float ar[8] = {a0.x, a0.y, a0.z, a0.w, a1.x, a1.y, a1.z, a1.w};
        float br[4] = {b0.x, b0.y, b0.z, b0.w};
#pragma unroll
        for (int i = 0; i < 8; i++)
#pragma unroll
            for (int j = 0; j < 4; j++)
                acc[i][j] = __fmaf_rn(ar[i], br[j], acc[i][j]);
    }
#pragma unroll
    for (int i = 0; i < 8; i++) {
        int co = (i < 4) ? (4 * ty + i) : (64 + 4 * ty + i - 4);
        float bi = bias[co];
        float* zo = g_z1 + (b * NHID + co) * P1;
#pragma unroll
        for (int j = 0; j < 4; j++) {
            int pos = posbase + 4 * tx + j;
            if (pos < P1) zo[pos] = fmaxf(__fadd_rn(acc[i][j], bi), 0.f);
        }
    }
}

// ---------------- conv2: 128->128, k2, s1, relu -- TENSOR (3-product) ----
__global__ void __launch_bounds__(256) k_conv2t(const float* __restrict__ bias) {
    __shared__ __align__(16) __nv_bfloat16 Ah[64 * 40];
    __shared__ __align__(16) __nv_bfloat16 Al[64 * 40];
    __shared__ __align__(16) __nv_bfloat16 Wh[128 * 40];
    __shared__ __align__(16) __nv_bfloat16 Wl[128 * 40];
    int b = blockIdx.y;
    int posbase = blockIdx.x * 64;
    int tid = threadIdx.x;
    int warp = tid >> 5, lane = tid & 31;
    int wm = warp >> 1, wn = warp & 1;
    const float* zin = g_z1 + b * (NHID * P1);

    int rowA = wm * 16 + ((lane >> 3) & 1) * 8 + (lane & 7);
    int colA = (lane >> 4) * 8;
    uint32_t aOff = (uint32_t)(rowA * 40 + colA) * 2;
    int rowB = wn * 64 + (lane >> 4) * 8 + (lane & 7);
    int colB = ((lane >> 3) & 1) * 8;
    uint32_t wOff = (uint32_t)(rowB * 40 + colB) * 2;
    uint32_t aHi = smaddr(Ah) + aOff, aLo = smaddr(Al) + aOff;
    uint32_t wHi = smaddr(Wh) + wOff, wLo = smaddr(Wl) + wOff;

    float d[8][4];
#pragma unroll
    for (int i = 0; i < 8; i++)
#pragma unroll
        for (int j = 0; j < 4; j++) d[i][j] = 0.f;

    for (int kb = 0; kb < 512; kb += 32) {
        __syncthreads();
        // A tile: 64 pos x 32 k' (im2col of z1, split on the fly)
#pragma unroll
        for (int it = 0; it < 8; it++) {
            int e = tid + 256 * it;             // 2048
            int pl = e & 63, kl = e >> 6;
            int k = kb + kl;
            int ci = k & 127, tap = k >> 7;
            int kh = tap >> 1, kw = tap & 1;
            int pos = posbase + pl;
            float v = 0.f;
            if (pos < P2) {
                int oh = pos / S2, ow = pos - oh * S2;
                v = zin[ci * P1 + (oh + kh) * S1 + ow + kw];
            }
            __nv_bfloat16 h = __float2bfloat16(v);
            Ah[pl * 40 + kl] = h;
            Al[pl * 40 + kl] = __float2bfloat16(v - __bfloat162float(h));
        }
#pragma unroll
        for (int it = 0; it < 2; it++) {
            int u = tid + 256 * it;             // 0..511
            int co = u >> 2, seg = u & 3;
            *(uint4*)&Wh[co * 40 + seg * 8] =
                *(const uint4*)&g_w2hi[co * 512 + kb + seg * 8];
            *(uint4*)&Wl[co * 40 + seg * 8] =
                *(const uint4*)&g_w2lo[co * 512 + kb + seg * 8];
        }
        __syncthreads();
#pragma unroll
        for (int ks = 0; ks < 2; ks++) {
            uint32_t ah0, ah1, ah2, ah3, al0, al1, al2, al3;
            LDSM_X4(ah0, ah1, ah2, ah3, aHi + ks * 32);
            LDSM_X4(al0, al1, al2, al3, aLo + ks * 32);
#pragma unroll
            for (int ntp = 0; ntp < 4; ntp++) {
                uint32_t bh0, bh1, bh2, bh3, bl0, bl1, bl2, bl3;
                LDSM_X4(bh0, bh1, bh2, bh3, wHi + ntp * (16 * 80) + ks * 32);
                LDSM_X4(bl0, bl1, bl2, bl3, wLo + ntp * (16 * 80) + ks * 32);
                MMA_BF16(d[2 * ntp],     ah0, ah1, ah2, ah3, bh0, bh1);
                MMA_BF16(d[2 * ntp],     ah0, ah1, ah2, ah3, bl0, bl1);
                MMA_BF16(d[2 * ntp],     al0, al1, al2, al3, bh0, bh1);
                MMA_BF16(d[2 * ntp + 1], ah0, ah1, ah2, ah3, bh2, bh3);
                MMA_BF16(d[2 * ntp + 1], ah0, ah1, ah2, ah3, bl2, bl3);
                MMA_BF16(d[2 * ntp + 1], al0, al1, al2, al3, bh2, bh3);
            }
        }
    }
    int r = lane >> 2, c2 = (lane & 3) * 2;
    int pos0 = posbase + wm * 16 + r;
    int pos1 = pos0 + 8;
#pragma unroll
    for (int nt = 0; nt < 8; nt++) {
        int co0 = wn * 64 + nt * 8 + c2;
        float bi0 = bias[co0], bi1 = bias[co0 + 1];
        float* z0 = g_z + (b * NHID + co0) * P2;
        float* z1p = z0 + P2;
        if (pos0 < P2) {
            z0[pos0]  = fmaxf(d[nt][0] + bi0, 0.f);
            z1p[pos0] = fmaxf(d[nt][1] + bi1, 0.f);
        }
        if (pos1 < P2) {
            z0[pos1]  = fmaxf(d[nt][2] + bi0, 0.f);
            z1p[pos1] = fmaxf(d[nt][3] + bi1, 0.f);
        }
    }
}

// ---------------- VQ: 1-product screen + exact repair + heavy repair -----
__device__ __forceinline__ float vq_exact(int grow, int code, float Z,
                                          const float* __restrict__ cb) {
    const float* zp = g_z + grow * NHID;
    const float* cp = cb + code * NHID;
    float acc = 0.f;
    for (int k = 0; k < NHID; k++) acc = __fmaf_rn(zp[k], cp[k], acc);
    float t = __fmaf_rn(-2.0f, acc, Z);
    return __fadd_rn(t, g_cnorm[code]);
}

extern __shared__ unsigned char sm_raw[];
__global__ void __launch_bounds__(256) k_vqt(const float* __restrict__ cb,
                                             const float* __restrict__ ew2,
                                             const float* __restrict__ eb2) {
    __nv_bfloat16* Ah = (__nv_bfloat16*)sm_raw;          // [128 rows][136]
    __nv_bfloat16* Bh = Ah + 128 * 136;                  // [2 bufs][64][136]
    float* cns   = (float*)(Bh + 2 * 64 * 136);          // 1024 f
    int*   scode = (int*)(cns + NK);                     // 128 i
    float* lred  = (float*)(scode + VQ_ROWS);            // 256 f (reused)
    int*   cand  = (int*)(lred + 256);                   // 128*12 i
    int*   riskyCnt  = cand + VQ_ROWS * 12;              // 1 i
    int*   riskyRows = riskyCnt + 1;                     // 128 i

    int row0 = blockIdx.x * VQ_ROWS;
    int tid = threadIdx.x, warp = tid >> 5, lane = tid & 31;
    const float* zrow = g_z + row0 * NHID;

    if (tid == 0) *riskyCnt = 0;
#pragma unroll 4
    for (int it = 0; it < 64; it++) {
        int e = tid + 256 * it;        // 16384
        int r = e >> 7, d = e & 127;
        Ah[r * 136 + d] = __float2bfloat16(zrow[e]);
    }
#pragma unroll
    for (int it = 0; it < 4; it++) cns[tid + 256 * it] = g_cnorm[tid + 256 * it];

    int m0 = warp * 16;
    int g = lane >> 2, cg = lane & 3;
    int r0 = m0 + g, r1 = r0 + 8;
    float Z0 = g_znorm[row0 + r0];
    float Z1 = g_znorm[row0 + r1];

    int rowA = m0 + ((lane >> 3) & 1) * 8 + (lane & 7);
    int colA = (lane >> 4) * 8;
    uint32_t aHi = smaddr(Ah) + (uint32_t)(rowA * 136 + colA) * 2;
    int rowB = (lane >> 4) * 8 + (lane & 7);
    int colB = ((lane >> 3) & 1) * 8;
    uint32_t bOffLane = (uint32_t)(rowB * 136 + colB) * 2;

    float v0a = 3.4e38f, v1a = 3.4e38f, v2a = 3.4e38f;
    int   i0a = 0, i1a = 0, i2a = 0;
    float v0b = 3.4e38f, v1b = 3.4e38f, v2b = 3.4e38f;
    int   i0b = 0, i1b = 0, i2b = 0;

#define VQ_ISSUE(c0_, buf_) {                                                  \
        int base_ = (c0_) * NHID;                                              \
        __nv_bfloat16* bhd = Bh + (buf_) * (64 * 136);                         \
        _Pragma("unroll")                                                      \
        for (int it = 0; it < 4; it++) {                                       \
            int e = tid + 256 * it;                                            \
            int r = e >> 4, seg = e & 15;                                      \
            cp_async16(bhd + r * 136 + seg * 8,                                \
                       g_cbhi + base_ + r * NHID + seg * 8);                   \
        }                                                                      \
    }

    VQ_ISSUE(0, 0); CP_COMMIT;

    for (int cc = 0; cc < 16; cc++) {
        int buf = cc & 1;
        int c0 = cc * 64;
        if (cc + 1 < 16) { VQ_ISSUE((cc + 1) * 64, (cc + 1) & 1); CP_COMMIT; CP_WAIT1; }
        else { CP_WAIT0; }
        __syncthreads();

        uint32_t bHiBase = smaddr(Bh + buf * (64 * 136)) + bOffLane;

        float dacc[8][4];
#pragma unroll
        for (int nt = 0; nt < 8; nt++)
#pragma unroll
            for (int j = 0; j < 4; j++) dacc[nt][j] = 0.f;

#pragma unroll
        for (int ks = 0; ks < 8; ks++) {
            uint32_t ah0, ah1, ah2, ah3;
            LDSM_X4(ah0, ah1, ah2, ah3, aHi + ks * 32);
#pragma unroll
            for (int ntp = 0; ntp < 4; ntp++) {
                uint32_t bh0, bh1, bh2, bh3;
                LDSM_X4(bh0, bh1, bh2, bh3, bHiBase + ntp * (16 * 272) + ks * 32);
                MMA_BF16(dacc[2 * ntp],     ah0, ah1, ah2, ah3, bh0, bh1);
                MMA_BF16(dacc[2 * ntp + 1], ah0, ah1, ah2, ah3, bh2, bh3);
            }
        }
#pragma unroll
        for (int nt = 0; nt < 8; nt++) {
            int cA = c0 + nt * 8 + cg * 2;
            float cnA = cns[cA];
            float cnB = cns[cA + 1];
            float s00 = __fmaf_rn(-2.f, dacc[nt][0], Z0) + cnA;
            float s01 = __fmaf_rn(-2.f, dacc[nt][1], Z0) + cnB;
            float s10 = __fmaf_rn(-2.f, dacc[nt][2], Z1) + cnA;
            float s11 = __fmaf_rn(-2.f, dacc[nt][3], Z1) + cnB;
            TOP3(s00, cA,     v0a, v1a, v2a, i0a, i1a, i2a);
            TOP3(s01, cA + 1, v0a, v1a, v2a, i0a, i1a, i2a);
            TOP3(s10, cA,     v0b, v1b, v2b, i0b, i1b, i2b);
            TOP3(s11, cA + 1, v0b, v1b, v2b, i0b, i1b, i2b);
        }
        __syncthreads();
    }
#undef VQ_ISSUE

    // store candidate lists (per row: 4 lanes x 3)
    cand[r0 * 12 + cg * 3 + 0] = i0a;
    cand[r0 * 12 + cg * 3 + 1] = i1a;
    cand[r0 * 12 + cg * 3 + 2] = i2a;
    cand[r1 * 12 + cg * 3 + 0] = i0b;
    cand[r1 * 12 + cg * 3 + 1] = i1b;
    cand[r1 * 12 + cg * 3 + 2] = i2b;

    // approx row-min across the 4 lanes sharing each row
    float rma = v0a, rmb = v0b;
#pragma unroll
    for (int off = 1; off < 4; off <<= 1) {
        rma = fminf(rma, __shfl_xor_sync(0xffffffffu, rma, off));
        rmb = fminf(rmb, __shfl_xor_sync(0xffffffffu, rmb, off));
    }

    // per-lane exact top-2 (value of 2nd only) among margin candidates
    float e0va = 3.4e38f, e1va = 3.4e38f; int e0ia = 0x7fffffff;
    float e0vb = 3.4e38f, e1vb = 3.4e38f; int e0ib = 0x7fffffff;
#define ADDEX(v, i, rm, grow, Z, e0v, e0i, e1v)                               \
    if ((v) <= (rm) + VQ_MARGIN) {                                            \
        float s_ = vq_exact(grow, i, Z, cb);                                  \
        if (s_ < e0v || (s_ == e0v && (i) < e0i)) {                           \
            e1v = e0v; e0v = s_; e0i = (i);                                   \
        } else if (s_ < e1v) e1v = s_;                                        \
    }
    ADDEX(v0a, i0a, rma, row0 + r0, Z0, e0va, e0ia, e1va);
    ADDEX(v1a, i1a, rma, row0 + r0, Z0, e0va, e0ia, e1va);
    ADDEX(v2a, i2a, rma, row0 + r0, Z0, e0va, e0ia, e1va);
    ADDEX(v0b, i0b, rmb, row0 + r1, Z1, e0vb, e0ib, e1vb);
    ADDEX(v1b, i1b, rmb, row0 + r1, Z1, e0vb, e0ib, e1vb);
    ADDEX(v2b, i2b, rmb, row0 + r1, Z1, e0vb, e0ib, e1vb);
#undef ADDEX

    // merge exact top-2 across the 4 lanes of each row
#pragma unroll
    for (int off = 1; off < 4; off <<= 1) {
        float ov = __shfl_xor_sync(0xffffffffu, e0va, off);
        int   oi = __shfl_xor_sync(0xffffffffu, e0ia, off);
        float o1 = __shfl_xor_sync(0xffffffffu, e1va, off);
        if (ov < e0va || (ov == e0va && oi < e0ia)) {
            e1va = fminf(o1, e0va); e0va = ov; e0ia = oi;
        } else {
            e1va = fminf(e1va, ov);
        }
        ov = __shfl_xor_sync(0xffffffffu, e0vb, off);
        oi = __shfl_xor_sync(0xffffffffu, e0ib, off);
        o1 = __shfl_xor_sync(0xffffffffu, e1vb, off);
        if (ov < e0vb || (ov == e0vb && oi < e0ib)) {
            e1vb = fminf(o1, e0vb); e0vb = ov; e0ib = oi;
        } else {
            e1vb = fminf(e1vb, ov);
        }
    }
    if (cg == 0) {
        scode[r0] = e0ia;
        scode[r1] = e0ib;
        if (e1va - e0va < RISK_THR) {
            int s = atomicAdd(riskyCnt, 1);
            riskyRows[s] = r0;
        }
        if (e1vb - e0vb < RISK_THR) {
            int s = atomicAdd(riskyCnt, 1);
            riskyRows[s] = r1;
        }
    }
    __syncthreads();

    // heavy repair: recompute EXACT z row from g_z1 for risky rows
    int nR = *riskyCnt;
    for (int rr = 0; rr < nR; rr++) {
        int r = riskyRows[rr];
        int grow = row0 + r;
        int bb = grow / P2;
        int nloc = grow - bb * P2;
        const float* z1b = g_z1 + bb * (NHID * P1);
        if (tid < 128) {
            int lin = nloc * 128 + tid;          // linear idx within [c][h][w]
            int c = lin / P2;
            int rem = lin - c * P2;
            int oh = rem / S2, ow = rem - oh * S2;
            float acc = 0.f;
#pragma unroll 4
            for (int k = 0; k < 512; k++) {
                int ci = k & 127, tap = k >> 7;
                float wv = ew2[c * 512 + ci * 4 + tap];
                float zv = z1b[ci * P1 + (oh + (tap >> 1)) * S1 + ow + (tap & 1)];
                acc = __fmaf_rn(zv, wv, acc);
            }
            lred[tid] = fmaxf(__fadd_rn(acc, eb2[c]), 0.f);   // exact z elem
        }
        __syncthreads();
        if (tid == 0) {
            float Zx = 0.f;
            for (int dd = 0; dd < 128; dd++)
                Zx = __fadd_rn(Zx, __fmul_rn(lred[dd], lred[dd]));
            lred[128] = Zx;
        }
        __syncthreads();
        if (tid < 12) {
            int code = cand[r * 12 + tid];
            float M = 0.f;
            for (int k = 0; k < NHID; k++)
                M = __fmaf_rn(lred[k], cb[code * NHID + k], M);
            lred[136 + tid] = __fadd_rn(__fmaf_rn(-2.f, M, lred[128]),
                                        cns[code]);
        }
        __syncthreads();
        if (tid == 0) {
            float bs = 3.4e38f; int bi2 = 0x7fffffff;
            for (int q2 = 0; q2 < 12; q2++) {
                float s = lred[136 + q2];
                int ii = cand[r * 12 + q2];
                if (s < bs || (s == bs && ii < bi2)) { bs = s; bi2 = ii; }
            }
            scode[r] = bi2;
        }
        __syncthreads();
    }

    // histogram (deferred until codes final)
    if (tid < VQ_ROWS) atomicAdd(&g_counts[scode[tid]], 1);
    __syncthreads();

    // gather: copy pre-split codebook rows (uint4) + squared-error partial
    float lsum = 0.f;
#pragma unroll
    for (int it = 0; it < 8; it++) {
        int e8 = tid + 256 * it;       // 2048 groups of 8 elems
        int r = e8 >> 4;
        int d0 = (e8 & 15) * 8;
        int code = scode[r];
        int cidx = code * NHID + d0;
        int qidx = (row0 + r) * NHID + d0;
        *(uint4*)&g_qhi[qidx] = *(const uint4*)&g_cbhi[cidx];
        *(uint4*)&g_qlo[qidx] = *(const uint4*)&g_cblo[cidx];
        float4 c0 = *(const float4*)&cb[cidx];
        float4 c1 = *(const float4*)&cb[cidx + 4];
        float4 z0 = *(const float4*)&zrow[r * NHID + d0];
        float4 z1 = *(const float4*)&zrow[r * NHID + d0 + 4];
        float df;
        df = c0.x - z0.x; lsum += df * df;
        df = c0.y - z0.y; lsum += df * df;
        df = c0.z - z0.z; lsum += df * df;
        df = c0.w - z0.w; lsum += df * df;
        df = c1.x - z1.x; lsum += df * df;
        df = c1.y - z1.y; lsum += df * df;
        df = c1.z - z1.z; lsum += df * df;
        df = c1.w - z1.w; lsum += df * df;
    }
    __syncthreads();
    lred[tid] = lsum;
    __syncthreads();
    for (int s = 128; s > 0; s >>= 1) {
        if (tid < s) lred[tid] += lred[tid + s];
        __syncthreads();
    }
    if (tid == 0) atomicAdd(&g_sse, (double)lred[0]);
}

// ---------------- dec1: convT 128->128, k2, s1, relu -- TENSOR (3-prod) --
__global__ void __launch_bounds__(256) k_dec1t(const float* __restrict__ bias) {
    __shared__ __align__(16) __nv_bfloat16 Ah[64 * 40];
    __shared__ __align__(16) __nv_bfloat16 Al[64 * 40];
    __shared__ __align__(16) __nv_bfloat16 Wh[128 * 40];
    __shared__ __align__(16) __nv_bfloat16 Wl[128 * 40];
    int b = blockIdx.y;
    int posbase = blockIdx.x * 64;
    int tid = threadIdx.x;
    int warp = tid >> 5, lane = tid & 31;
    int wm = warp >> 1, wn = warp & 1;
    const __nv_bfloat16* qhb = g_qhi + b * (NHID * P2);
    const __nv_bfloat16* qlb = g_qlo + b * (NHID * P2);

    int rowA = wm * 16 + ((lane >> 3) & 1) * 8 + (lane & 7);
    int colA = (lane >> 4) * 8;
    uint32_t aOff = (uint32_t)(rowA * 40 + colA) * 2;
    int rowB = wn * 64 + (lane >> 4) * 8 + (lane & 7);
    int colB = ((lane >> 3) & 1) * 8;
    uint32_t wOff = (uint32_t)(rowB * 40 + colB) * 2;
    uint32_t aHi = smaddr(Ah) + aOff, aLo = smaddr(Al) + aOff;
    uint32_t wHi = smaddr(Wh) + wOff, wLo = smaddr(Wl) + wOff;

    float d[8][4];
#pragma unroll
    for (int i = 0; i < 8; i++)
#pragma unroll
        for (int j = 0; j < 4; j++) d[i][j] = 0.f;

    for (int kb = 0; kb < 512; kb += 32) {
        __syncthreads();
#pragma unroll
        for (int it = 0; it < 8; it++) {
            int e = tid + 256 * it;             // 2048
            int pl = e & 63, kl = e >> 6;
            int k = kb + kl;
            int ci = k >> 2, kh = (k >> 1) & 1, kw = k & 1;
            int pos = posbase + pl;
            __nv_bfloat16 vh = __float2bfloat16(0.f), vl = vh;
            if (pos < P1) {
                int oh = pos / S1, ow = pos - oh * S1;
                int ih = oh - kh, iw = ow - kw;
                if ((unsigned)ih < (unsigned)S2 && (unsigned)iw < (unsigned)S2) {
                    int idx = ci * P2 + ih * S2 + iw;
                    vh = qhb[idx];
                    vl = qlb[idx];
                }
            }
            Ah[pl * 40 + kl] = vh;
            Al[pl * 40 + kl] = vl;
        }
#pragma unroll
        for (int it = 0; it < 2; it++) {
            int u = tid + 256 * it;             // 0..511
            int co = u >> 2, seg = u & 3;
            *(uint4*)&Wh[co * 40 + seg * 8] =
                *(const uint4*)&g_whi[co * 512 + kb + seg * 8];
            *(uint4*)&Wl[co * 40 + seg * 8] =
                *(const uint4*)&g_wlo[co * 512 + kb + seg * 8];
        }
        __syncthreads();
#pragma unroll
        for (int ks = 0; ks < 2; ks++) {
            uint32_t ah0, ah1, ah2, ah3, al0, al1, al2, al3;
            LDSM_X4(ah0, ah1, ah2, ah3, aHi + ks * 32);
            LDSM_X4(al0, al1, al2, al3, aLo + ks * 32);
#pragma unroll
            for (int ntp = 0; ntp < 4; ntp++) {
                uint32_t bh0, bh1, bh2, bh3, bl0, bl1, bl2, bl3;
                LDSM_X4(bh0, bh1, bh2, bh3, wHi + ntp * (16 * 80) + ks * 32);
                LDSM_X4(bl0, bl1, bl2, bl3, wLo + ntp * (16 * 80) + ks * 32);
                MMA_BF16(d[2 * ntp],     ah0, ah1, ah2, ah3, bh0, bh1);
                MMA_BF16(d[2 * ntp],     ah0, ah1, ah2, ah3, bl0, bl1);
                MMA_BF16(d[2 * ntp],     al0, al1, al2, al3, bh0, bh1);
                MMA_BF16(d[2 * ntp + 1], ah0, ah1, ah2, ah3, bh2, bh3);
                MMA_BF16(d[2 * ntp + 1], ah0, ah1, ah2, ah3, bl2, bl3);
                MMA_BF16(d[2 * ntp + 1], al0, al1, al2, al3, bh2, bh3);
            }
        }
    }
    int r = lane >> 2, c2 = (lane & 3) * 2;
    int pos0 = posbase + wm * 16 + r;
    int pos1 = pos0 + 8;
#pragma unroll
    for (int nt = 0; nt < 8; nt++) {
        int co0 = wn * 64 + nt * 8 + c2;
        float bi0 = bias[co0], bi1 = bias[co0 + 1];
        float* y0 = g_y + (b * NHID + co0) * P1;
        float* y1 = y0 + P1;
        if (pos0 < P1) {
            y0[pos0] = fmaxf(d[nt][0] + bi0, 0.f);
            y1[pos0] = fmaxf(d[nt][1] + bi1, 0.f);
        }
        if (pos1 < P1) {
            y0[pos1] = fmaxf(d[nt][2] + bi0, 0.f);
            y1[pos1] = fmaxf(d[nt][3] + bi1, 0.f);
        }
    }
}

// ---------------- dec2: convT 128->3, k4, s2 -> x_recon ----------------
extern __shared__ float sm_d2[];
__global__ void __launch_bounds__(192) k_dec2(const float* __restrict__ w,
                                              const float* __restrict__ bias,
                                              float* __restrict__ out) {
    float* sy = sm_d2;           // [2 rows][128 ci][32 iw] = 8192
    float* sw = sm_d2 + 8192;    // full weights 128*3*16 = 6144
    int b = blockIdx.y, t = blockIdx.x;   // outputs oh = 2t, 2t+1
    int tid = threadIdx.x;
    const float* yb = g_y + b * (NHID * P1);

    for (int e = tid; e < 8192; e += 192) {
        int r = e >> 12;
        int rem = e & 4095;
        int ci = rem >> 5, iw = rem & 31;
        int ih = t - r;
        float v = 0.f;
        if (iw < S1 && (unsigned)ih < (unsigned)S1) v = yb[ci * P1 + ih * S1 + iw];
        sy[e] = v;
    }
    for (int e = tid; e < 6144; e += 192) sw[e] = w[e];
    __syncthreads();

    int co = tid >> 6;      // 0..2
    int ow = tid & 63;
    int pw = ow & 1;
    int iw0 = ow >> 1;
    int iw1 = iw0 - 1;
    bool ok1 = (iw1 >= 0);
    int iw1c = ok1 ? iw1 : 0;

    float accE = 0.f, accO = 0.f;
#pragma unroll 4
    for (int ci = 0; ci < NHID; ci++) {
        float y00 = sy[ci * 32 + iw0];
        float y01 = ok1 ? sy[ci * 32 + iw1c] : 0.f;
        float y10 = sy[4096 + ci * 32 + iw0];
        float y11 = ok1 ? sy[4096 + ci * 32 + iw1c] : 0.f;
        const float* wb = sw + ci * 48 + co * 16;
        accE += y00 * wb[pw]      + y01 * wb[pw + 2]
              + y10 * wb[8 + pw]  + y11 * wb[8 + pw + 2];
        accO += y00 * wb[4 + pw]  + y01 * wb[4 + pw + 2]
              + y10 * wb[12 + pw] + y11 * wb[12 + pw + 2];
    }
    float bi = bias[co];
    int base = b * (3 * 4096) + co * 4096 + (2 * t) * 64 + ow;
    out[base]      = accE + bi;
    out[base + 64] = accO + bi;
}

// ---------------- finalize: loss + perplexity ----------------
__global__ void k_final(float* __restrict__ out) {
    __shared__ double sd[1024];
    int t = threadIdx.x;
    double pr = (double)g_counts[t] / (double)NROWS;
    sd[t] = pr * log(pr + 1e-10);
    __syncthreads();
    for (int s = 512; s > 0; s >>= 1) {
        if (t < s) sd[t] += sd[t + s];
        __syncthreads();
    }
    if (t == 0) {
        out[786432] = (float)(1.25 * g_sse / NELEMF);  // loss = (1+beta)*mse
        out[786433] = (float)exp(-sd[0]);              // perplexity
    }
}

// ---------------- launch ----------------
extern "C" void kernel_launch(void* const* d_in, const int* in_sizes, int n_in,
                              void* d_out, int out_size) {
    const float* x   = (const float*)d_in[0];
    const float* ew1 = (const float*)d_in[1];
    const float* eb1 = (const float*)d_in[2];
    const float* ew2 = (const float*)d_in[3];
    const float* eb2 = (const float*)d_in[4];
    const float* cb  = (const float*)d_in[5];
    const float* dw1 = (const float*)d_in[6];
    const float* db1 = (const float*)d_in[7];
    const float* dw2 = (const float*)d_in[8];
    const float* db2 = (const float*)d_in[9];
    float* out = (float*)d_out;

    // k_vqt smem: Ah 34816 + Bh 34816 + cns 4096 + scode 512 + lred 1024
    //             + cand 6144 + riskyCnt/Rows 516  => 81924 -> 81928 (align)
    int vq_smem = 34816 + 34816 + 4096 + 512 + 1024 + 6144 + 520;
    cudaFuncSetAttribute(k_vqt, cudaFuncAttributeMaxDynamicSharedMemorySize,
                         vq_smem);
    cudaFuncSetAttribute(k_dec2, cudaFuncAttributeMaxDynamicSharedMemorySize,
                         (8192 + 6144) * (int)sizeof(float));

    k_prep<<<512, 256>>>(cb, dw1, ew2);
    k_conv1<<<dim3(16, NB), 256>>>(x, ew1, eb1);
    k_conv2t<<<dim3(15, NB), 256>>>(eb2);
    k_znorm<<<NROWS / 64, 256>>>();
    k_vqt<<<NROWS / VQ_ROWS, 256, vq_smem>>>(cb, ew2, eb2);
    k_dec1t<<<dim3(16, NB), 256>>>(db1);
    k_dec2<<<dim3(32, NB), 192, (8192 + 6144) * (int)sizeof(float)>>>(dw2, db2, out);
    k_final<<<1, 1024>>>(out);
}